// round 1
// baseline (speedup 1.0000x reference)
#include <cuda_runtime.h>
#include <cstdint>

// Shapes (fixed for this problem)
#define M_TOK 8192   // B*C tokens
#define Dm    512    // d_model
#define Kcb   8192   // codebook size
#define Ff    129    // stft bins
#define Cc    64     // channels (for pos_emb)

// Main-kernel tiling
#define NSPLIT  4        // K split across blockIdx.y
#define KSPL    (Kcb / NSPLIT)   // 2048 codes per split
#define MT      128      // token tile
#define NT      128      // code tile (chunk)
#define DC      16       // depth (d) per smem stage
#define KCHUNKS (KSPL / NT)      // 16 chunks per split
#define NDST    (Dm / DC)        // 32 depth stages

// -------- scratch (static device globals: no runtime allocation) --------
__device__ float g_z[M_TOK * Dm];          // projected tokens  (16 MB)
__device__ float g_e2[Kcb];                // |e_k|^2
__device__ float g_pmin[NSPLIT * M_TOK];   // per-split partial min score
__device__ int   g_pidx[NSPLIT * M_TOK];   // per-split partial argmin
__device__ float g_loss;                   // commit-loss accumulator

// packed fp32x2 FMA (sm_100+): d.lo += a.lo*b.lo ; d.hi += a.hi*b.hi
#define FMA2(accv, av, bv) \
    asm("fma.rn.f32x2 %0, %1, %2, %0;" : "+l"(accv) : "l"(av), "l"(bv))

// ======================= kernel 1: e2 + zero loss =======================
__global__ __launch_bounds__(256) void k_e2(const float* __restrict__ cb) {
    int row  = blockIdx.x * 8 + (threadIdx.x >> 5);
    int lane = threadIdx.x & 31;
    const float* r = cb + row * Dm;
    float s = 0.f;
    #pragma unroll 4
    for (int i = lane; i < Dm; i += 32) { float v = r[i]; s = fmaf(v, v, s); }
    #pragma unroll
    for (int o = 16; o; o >>= 1) s += __shfl_xor_sync(0xffffffffu, s, o);
    if (lane == 0) g_e2[row] = s;
    if (blockIdx.x == 0 && threadIdx.x == 0) g_loss = 0.f;
}

// ======================= kernel 2: z = x @ W + b ========================
// One block = 32 tokens, 256 threads; thread t owns columns d=t and d=t+256.
__global__ __launch_bounds__(256) void k_zgemm(const float* __restrict__ x,
                                               const float* __restrict__ W,
                                               const float* __restrict__ b) {
    __shared__ float xs[32][Ff];
    const int m0 = blockIdx.x * 32;
    const int t  = threadIdx.x;

    for (int i = t; i < 32 * Ff; i += 256) {
        int r = i / Ff, c = i - r * Ff;
        xs[r][c] = x[(m0 + r) * Ff + c];
    }
    __syncthreads();

    float acc0[32], acc1[32];
    const float b0 = b[t], b1 = b[t + 256];
    #pragma unroll
    for (int i = 0; i < 32; i++) { acc0[i] = b0; acc1[i] = b1; }

    float w0 = W[t], w1 = W[t + 256];
    for (int f = 0; f < Ff; f++) {
        float nw0 = 0.f, nw1 = 0.f;
        if (f + 1 < Ff) { nw0 = W[(f + 1) * Dm + t]; nw1 = W[(f + 1) * Dm + t + 256]; }
        #pragma unroll
        for (int i = 0; i < 32; i++) {
            float xv = xs[i][f];
            acc0[i] = fmaf(xv, w0, acc0[i]);
            acc1[i] = fmaf(xv, w1, acc1[i]);
        }
        w0 = nw0; w1 = nw1;
    }
    #pragma unroll
    for (int i = 0; i < 32; i++) {
        g_z[(m0 + i) * Dm + t]       = acc0[i];
        g_z[(m0 + i) * Dm + t + 256] = acc1[i];
    }
}

// ============ kernel 3: fused dist-GEMM + running argmin ================
// Grid (M/MT, NSPLIT). Block 256 threads; micro-tile 8 tokens x 8 codes.
// z stored duplicated in SMEM as (z,z) pairs so FFMA2 lanes carry 2 codes.
__global__ __launch_bounds__(256, 2) void k_argmin(const float* __restrict__ cb) {
    __shared__ float Zs[2][DC][2 * MT];   // 32 KB (duplicated z)
    __shared__ float Cs[2][DC][NT];       // 16 KB

    const int t  = threadIdx.x;
    const int tx = t & 15;     // code group
    const int ty = t >> 4;     // token group
    const int m0  = blockIdx.x * MT;
    const int ks0 = blockIdx.y * KSPL;

    // fill-index precompute: two 512-float4 passes per stage
    const int rowA = t >> 2,         c4A = (t & 3) * 4;          // li = t
    const int rowB = (t + 256) >> 2, c4B = ((t + 256) & 3) * 4;  // li = t+256

    unsigned long long acc[8][4];
    float rmin[8]; int ridx[8];
    #pragma unroll
    for (int i = 0; i < 8; i++) { rmin[i] = __int_as_float(0x7f800000); ridx[i] = 0x7fffffff; }

    for (int ch = 0; ch < KCHUNKS; ch++) {
        const int n0 = ks0 + ch * NT;
        #pragma unroll
        for (int i = 0; i < 8; i++)
            #pragma unroll
            for (int j = 0; j < 4; j++) acc[i][j] = 0ull;

        // ---- prologue: fill stage 0 (d0 = 0) ----
        {
            float4 vzA = *(const float4*)&g_z[(m0 + rowA) * Dm + c4A];
            float4 vzB = *(const float4*)&g_z[(m0 + rowB) * Dm + c4B];
            float4 vcA = *(const float4*)&cb [(n0 + rowA) * Dm + c4A];
            float4 vcB = *(const float4*)&cb [(n0 + rowB) * Dm + c4B];
            Cs[0][c4A+0][rowA]=vcA.x; Cs[0][c4A+1][rowA]=vcA.y; Cs[0][c4A+2][rowA]=vcA.z; Cs[0][c4A+3][rowA]=vcA.w;
            Cs[0][c4B+0][rowB]=vcB.x; Cs[0][c4B+1][rowB]=vcB.y; Cs[0][c4B+2][rowB]=vcB.z; Cs[0][c4B+3][rowB]=vcB.w;
            *(float2*)&Zs[0][c4A+0][2*rowA] = make_float2(vzA.x, vzA.x);
            *(float2*)&Zs[0][c4A+1][2*rowA] = make_float2(vzA.y, vzA.y);
            *(float2*)&Zs[0][c4A+2][2*rowA] = make_float2(vzA.z, vzA.z);
            *(float2*)&Zs[0][c4A+3][2*rowA] = make_float2(vzA.w, vzA.w);
            *(float2*)&Zs[0][c4B+0][2*rowB] = make_float2(vzB.x, vzB.x);
            *(float2*)&Zs[0][c4B+1][2*rowB] = make_float2(vzB.y, vzB.y);
            *(float2*)&Zs[0][c4B+2][2*rowB] = make_float2(vzB.z, vzB.z);
            *(float2*)&Zs[0][c4B+3][2*rowB] = make_float2(vzB.w, vzB.w);
        }
        __syncthreads();

        // ---- mainloop over depth stages (double-buffered) ----
        for (int ds = 0; ds < NDST; ds++) {
            const int cur = ds & 1;
            float4 vzA, vzB, vcA, vcB;
            const bool pf = (ds + 1 < NDST);
            if (pf) {
                const int d0n = (ds + 1) * DC;
                vzA = *(const float4*)&g_z[(m0 + rowA) * Dm + d0n + c4A];
                vzB = *(const float4*)&g_z[(m0 + rowB) * Dm + d0n + c4B];
                vcA = *(const float4*)&cb [(n0 + rowA) * Dm + d0n + c4A];
                vcB = *(const float4*)&cb [(n0 + rowB) * Dm + d0n + c4B];
            }

            // compute 16 depth steps from stage `cur`
            #pragma unroll
            for (int kc = 0; kc < DC; kc++) {
                const ulonglong2* ap = (const ulonglong2*)&Zs[cur][kc][ty * 16];
                ulonglong2 a0 = ap[0], a1 = ap[1], a2 = ap[2], a3 = ap[3];
                const ulonglong2* bp = (const ulonglong2*)&Cs[cur][kc][tx * 8];
                ulonglong2 bb0 = bp[0], bb1 = bp[1];
                unsigned long long A[8] = {a0.x,a0.y,a1.x,a1.y,a2.x,a2.y,a3.x,a3.y};
                unsigned long long Bv[4] = {bb0.x,bb0.y,bb1.x,bb1.y};
                #pragma unroll
                for (int i = 0; i < 8; i++)
                    #pragma unroll
                    for (int j = 0; j < 4; j++)
                        FMA2(acc[i][j], A[i], Bv[j]);
            }

            if (pf) {
                const int nx = cur ^ 1;
                Cs[nx][c4A+0][rowA]=vcA.x; Cs[nx][c4A+1][rowA]=vcA.y; Cs[nx][c4A+2][rowA]=vcA.z; Cs[nx][c4A+3][rowA]=vcA.w;
                Cs[nx][c4B+0][rowB]=vcB.x; Cs[nx][c4B+1][rowB]=vcB.y; Cs[nx][c4B+2][rowB]=vcB.z; Cs[nx][c4B+3][rowB]=vcB.w;
                *(float2*)&Zs[nx][c4A+0][2*rowA] = make_float2(vzA.x, vzA.x);
                *(float2*)&Zs[nx][c4A+1][2*rowA] = make_float2(vzA.y, vzA.y);
                *(float2*)&Zs[nx][c4A+2][2*rowA] = make_float2(vzA.z, vzA.z);
                *(float2*)&Zs[nx][c4A+3][2*rowA] = make_float2(vzA.w, vzA.w);
                *(float2*)&Zs[nx][c4B+0][2*rowB] = make_float2(vzB.x, vzB.x);
                *(float2*)&Zs[nx][c4B+1][2*rowB] = make_float2(vzB.y, vzB.y);
                *(float2*)&Zs[nx][c4B+2][2*rowB] = make_float2(vzB.z, vzB.z);
                *(float2*)&Zs[nx][c4B+3][2*rowB] = make_float2(vzB.w, vzB.w);
            }
            __syncthreads();
        }

        // ---- epilogue: score = e2 - 2*dot, running argmin ----
        const int kb = n0 + tx * 8;
        #pragma unroll
        for (int i = 0; i < 8; i++) {
            #pragma unroll
            for (int j = 0; j < 4; j++) {
                float dlo = __uint_as_float((unsigned)(acc[i][j] & 0xffffffffull));
                float dhi = __uint_as_float((unsigned)(acc[i][j] >> 32));
                int k0 = kb + 2 * j;
                float s0 = fmaf(-2.f, dlo, g_e2[k0]);
                float s1 = fmaf(-2.f, dhi, g_e2[k0 + 1]);
                if (s0 < rmin[i] || (s0 == rmin[i] && k0     < ridx[i])) { rmin[i] = s0; ridx[i] = k0;     }
                if (s1 < rmin[i] || (s1 == rmin[i] && k0 + 1 < ridx[i])) { rmin[i] = s1; ridx[i] = k0 + 1; }
            }
        }
    }

    // ---- cross-thread (tx) reduction via smem reuse ----
    __syncthreads();
    float* smin = (float*)Zs;   // 128*16 floats
    int*   sidx = (int*)Cs;     // 128*16 ints
    #pragma unroll
    for (int i = 0; i < 8; i++) {
        int m = ty * 8 + i;
        smin[m * 16 + tx] = rmin[i];
        sidx[m * 16 + tx] = ridx[i];
    }
    __syncthreads();
    if (t < MT) {
        float bs = smin[t * 16]; int bi = sidx[t * 16];
        #pragma unroll
        for (int j = 1; j < 16; j++) {
            float s = smin[t * 16 + j]; int ix = sidx[t * 16 + j];
            if (s < bs || (s == bs && ix < bi)) { bs = s; bi = ix; }
        }
        g_pmin[blockIdx.y * M_TOK + m0 + t] = bs;
        g_pidx[blockIdx.y * M_TOK + m0 + t] = bi;
    }
}

// ======= kernel 4: combine splits, gather, out = q + pos, loss ==========
__global__ __launch_bounds__(256) void k_out(const float* __restrict__ cb,
                                             const float* __restrict__ pos,
                                             float* __restrict__ out) {
    const int m = blockIdx.x;
    const int t = threadIdx.x;
    __shared__ int sIdx;
    __shared__ float red[8];

    if (t == 0) {
        float bs = g_pmin[m]; int bi = g_pidx[m];
        #pragma unroll
        for (int p = 1; p < NSPLIT; p++) {
            float s = g_pmin[p * M_TOK + m]; int ix = g_pidx[p * M_TOK + m];
            if (s < bs || (s == bs && ix < bi)) { bs = s; bi = ix; }
        }
        sIdx = bi;
    }
    __syncthreads();
    const int idx = sIdx;
    const float* q  = cb  + (long)idx * Dm;
    const float* zr = g_z + (long)m   * Dm;
    const float* pr = pos + (m & (Cc - 1)) * Dm;

    float lsum = 0.f;
    #pragma unroll
    for (int r = 0; r < 2; r++) {
        int d = t + r * 256;
        float qv = q[d], zv = zr[d];
        out[(long)m * Dm + d] = qv + pr[d];
        float df = qv - zv;
        lsum = fmaf(df, df, lsum);
    }
    #pragma unroll
    for (int o = 16; o; o >>= 1) lsum += __shfl_xor_sync(0xffffffffu, lsum, o);
    if ((t & 31) == 0) red[t >> 5] = lsum;
    __syncthreads();
    if (t == 0) {
        float s = 0.f;
        #pragma unroll
        for (int w = 0; w < 8; w++) s += red[w];
        atomicAdd(&g_loss, s);
    }
}

// ================= kernel 5: write commit_loss scalar ===================
__global__ void k_final(float* __restrict__ out, int out_size) {
    if (out_size > M_TOK * Dm)
        out[M_TOK * Dm] = g_loss * (1.f / (float)((long)M_TOK * Dm));
}

// ============================ launcher ==================================
extern "C" void kernel_launch(void* const* d_in, const int* in_sizes, int n_in,
                              void* d_out, int out_size) {
    const float* x   = (const float*)d_in[0];  // [B,C,F]
    const float* W   = (const float*)d_in[1];  // [F,D]
    const float* b   = (const float*)d_in[2];  // [D]
    const float* cb  = (const float*)d_in[3];  // [K,D]
    const float* pos = (const float*)d_in[4];  // [1,C,D]
    float* out = (float*)d_out;

    k_e2    <<<Kcb / 8, 256>>>(cb);
    k_zgemm <<<M_TOK / 32, 256>>>(x, W, b);
    k_argmin<<<dim3(M_TOK / MT, NSPLIT), 256>>>(cb);
    k_out   <<<M_TOK, 256>>>(cb, pos, out);
    k_final <<<1, 1>>>(out, out_size);
}